// round 17
// baseline (speedup 1.0000x reference)
#include <cuda_runtime.h>
#include <cuda_bf16.h>
#include <cuda_fp8.h>
#include <cstdint>

// ============================================================================
// y[M,N] = fq(x*sx)[M,K] @ fq(w*sw)[N,K]^T / (sx*sw) + bias, bf16-rounded,
// stored as f32. fp8 mma.sync.m16n8k32 (bit-exact, R9+).
// R17: bulk-DMA producer. Quant pre-pass writes pre-swizzled tile-chunk-
// contiguous fp8; one elected thread issues 2 x cp.async.bulk (16KB) per chunk
// with mbarrier expect_tx completion. Kills the 2048 cp.async + address-ALU
// per chunk that was eating issue slots (alu=33% in R16).
// ============================================================================
#define GM 8192
#define GN 4096
#define GK 4096

#define BM 128
#define BN 128
#define BK 128                     // fp8 bytes per K chunk
#define K_CHUNKS (GK / BK)         // 32
#define NTILES ((GM / BM) * (GN / BN))   // 2048
#define STAGES 3
#define THREADS 256

#define A_BYTES (BM * BK)          // 16384
#define B_BYTES (BN * BK)          // 16384
#define STAGE_BYTES (A_BYTES + B_BYTES)      // 32768
#define STAGE_SMEM (STAGES * STAGE_BYTES)    // 98304
#define SMEM_TOTAL (STAGE_SMEM + 64)         // + mbarriers; 2 CTAs/SM

// fp8 scratch, TILED + PRE-SWIZZLED:
//   g_Aq: [mt(64)][kc(32)][16384]   g_Bq: [nt(32)][kc(32)][16384]
// within a 16KB block: offset(r,kk) = (r*128+kk) ^ ((r&7)<<4)  (SW pattern
// identical to the cp_async16 image used since R9 — LDSM mapping unchanged)
__device__ __align__(1024) unsigned char g_Aq[(size_t)GM * GK];
__device__ __align__(1024) unsigned char g_Bq[(size_t)GN * GK];

// ============================================================================
// helpers
// ============================================================================
__device__ __forceinline__ uint32_t smem_to_u32(const void* p) {
    uint32_t a;
    asm("{ .reg .u64 t; cvta.to.shared.u64 t, %1; cvt.u32.u64 %0, t; }" : "=r"(a) : "l"(p));
    return a;
}

#define MBARRIER_INIT(addr, cnt) \
    asm volatile("mbarrier.init.shared.b64 [%0], %1;" \
                 :: "r"((uint32_t)(addr)), "r"((uint32_t)(cnt)) : "memory")
#define MBARRIER_ARRIVE(addr) \
    asm volatile("mbarrier.arrive.shared.b64 _, [%0];" :: "r"((uint32_t)(addr)) : "memory")
#define MBARRIER_EXPECT_TX(addr, bytes) \
    asm volatile("mbarrier.arrive.expect_tx.shared.b64 _, [%0], %1;" \
                 :: "r"((uint32_t)(addr)), "r"((uint32_t)(bytes)) : "memory")
#define FENCE_PROXY_ASYNC() \
    asm volatile("fence.proxy.async.shared::cta;" ::: "memory")

// 1-D bulk async copy global -> shared, completion via mbarrier tx-count
__device__ __forceinline__ void bulk_g2s(uint32_t dst_smem, const void* src,
                                         uint32_t bytes, uint32_t mbar) {
    asm volatile(
        "cp.async.bulk.shared::cluster.global.mbarrier::complete_tx::bytes "
        "[%0], [%1], %2, [%3];"
        :: "r"(dst_smem), "l"(src), "r"(bytes), "r"(mbar) : "memory");
}

#define MBAR_WAIT(mbar, parity) do { \
    uint32_t _m = (uint32_t)(mbar); \
    uint32_t _p = (uint32_t)(parity); \
    uint32_t _done; \
    asm volatile("{\n\t.reg .pred p;\n\t" \
        "mbarrier.try_wait.parity.acquire.cta.shared::cta.b64 p, [%1], %2;\n\t" \
        "selp.b32 %0, 1, 0, p;\n\t}" : "=r"(_done) : "r"(_m), "r"(_p) : "memory"); \
    if (!_done) { \
        asm volatile("{\n\t.reg .pred P1;\n\t" \
            "WL_%=:\n\t" \
            "mbarrier.try_wait.parity.acquire.cta.shared::cta.b64 P1, [%0], %1, 0x989680;\n\t" \
            "@P1 bra.uni WD_%=;\n\t" \
            "bra.uni WL_%=;\n\t" \
            "WD_%=:\n\t}" :: "r"(_m), "r"(_p) : "memory"); \
    } \
} while (0)

__device__ __forceinline__ void ldmatrix_x4(uint32_t& r0, uint32_t& r1,
                                            uint32_t& r2, uint32_t& r3, uint32_t addr) {
    asm volatile("ldmatrix.sync.aligned.m8n8.x4.shared.b16 {%0,%1,%2,%3}, [%4];"
                 : "=r"(r0), "=r"(r1), "=r"(r2), "=r"(r3) : "r"(addr));
}

__device__ __forceinline__ void mma_e4m3(float* d, const uint32_t* a,
                                         uint32_t b0, uint32_t b1) {
    asm volatile(
        "mma.sync.aligned.m16n8k32.row.col.f32.e4m3.e4m3.f32 "
        "{%0,%1,%2,%3}, {%4,%5,%6,%7}, {%8,%9}, {%0,%1,%2,%3};"
        : "+f"(d[0]), "+f"(d[1]), "+f"(d[2]), "+f"(d[3])
        : "r"(a[0]), "r"(a[1]), "r"(a[2]), "r"(a[3]), "r"(b0), "r"(b1));
}

// ----------------------------------------------------------------------------
// Exact reference fake-quant (E4M3). Bit-exact vs reference (R8-R16: rel=0).
// ----------------------------------------------------------------------------
__device__ __forceinline__ float fake_quant_e4m3(float y) {
    float yc = fminf(fmaxf(y, -448.0f), 448.0f);
    float mag = fabsf(yc);
    if (mag == 0.0f) return 0.0f;
    int e = (int)((__float_as_uint(mag) >> 23) & 0xFF) - 127;
    if (e < -6) e = -6;
    float stepinv = __int_as_float((uint32_t)(127 + 3 - e) << 23);  // 2^(3-e)
    float step    = __int_as_float((uint32_t)(127 - 3 + e) << 23);  // 2^(e-3)
    return rintf(yc * stepinv) * step;
}

// ============================================================================
// Merged quantization -> tiled, pre-swizzled fp8 scratch.
// Thread handles 8 consecutive k of one row; 8B block keeps swizzle intact
// (XOR touches bits [6:4] only; kk%8 bits unaffected).
// ============================================================================
#define X_TOTAL8 (GM * GK / 8)
#define W_TOTAL8 (GN * GK / 8)

__global__ void quant_both_kernel(const float* __restrict__ x,
                                  const float* __restrict__ wgt,
                                  const float* __restrict__ xs,
                                  const float* __restrict__ ws) {
    int idx = blockIdx.x * blockDim.x + threadIdx.x;
    const float* src;
    unsigned char* dst;
    float s;
    if (idx < X_TOTAL8) {
        src = x; dst = g_Aq; s = xs[0];
    } else {
        idx -= X_TOTAL8;
        if (idx >= W_TOTAL8) return;
        src = wgt; dst = g_Bq; s = ws[0];
    }
    size_t e0 = (size_t)idx * 8;
    int row = (int)(e0 >> 12);       // / 4096
    int k   = (int)(e0 & 4095);

    float4 v0 = *reinterpret_cast<const float4*>(src + e0);
    float4 v1 = *reinterpret_cast<const float4*>(src + e0 + 4);
    float f[8] = {v0.x, v0.y, v0.z, v0.w, v1.x, v1.y, v1.z, v1.w};
    uint64_t out8 = 0;
#pragma unroll
    for (int i = 0; i < 8; i++) {
        float q = fake_quant_e4m3(f[i] * s);
        uint8_t b = __nv_cvt_float_to_fp8(q, __NV_SATFINITE, __NV_E4M3);
        out8 |= (uint64_t)b << (8 * i);
    }

    const int tile = row >> 7, kc = k >> 7;
    const int r = row & 127, kk = k & 127;
    uint32_t sw = (uint32_t)((r << 7) | kk) ^ (uint32_t)((r & 7) << 4);
    size_t off = (((size_t)tile * K_CHUNKS + kc) << 14) + sw;
    *reinterpret_cast<uint64_t*>(dst + off) = out8;
}

// ============================================================================
// Persistent FP8 GEMM: bulk-DMA producer (1 elected thread, 2x16KB per chunk),
// 8 consumer warps (32x64), 3-stage mbarrier pipeline, 2 CTAs/SM.
// ============================================================================
__global__ void __launch_bounds__(THREADS, 2) gemm_kernel(
    const float* __restrict__ bias,
    const float* __restrict__ xs, const float* __restrict__ ws,
    float* __restrict__ out) {
    extern __shared__ __align__(1024) char smem[];
    const uint32_t smem_base = smem_to_u32(smem);
    const uint32_t mbar_base = smem_base + STAGE_SMEM;   // full[s]@16s, empty[s]@16s+8
    const int tid = threadIdx.x;
    const int w = tid >> 5, l = tid & 31;
    const int warp_m = (w >> 1) * 32;
    const int warp_n = (w & 1) * 64;
    const int bid = blockIdx.x, gsz = gridDim.x;

    if (tid == 0) {
#pragma unroll
        for (int s = 0; s < STAGES; s++) {
            MBARRIER_INIT(mbar_base + 16 * s, 1);            // full[s]: expect_tx arrive
            MBARRIER_INIT(mbar_base + 16 * s + 8, THREADS);  // empty[s]: all consumers
        }
        FENCE_PROXY_ASYNC();
    }
    __syncthreads();

    const int myTiles = (NTILES - bid + gsz - 1) / gsz;
    const int L = myTiles * K_CHUNKS;

    // producer (tid 0 only): stream chunk p -> stage s
    auto produce = [&](int p, int s, int u) {
        const int ti = p >> 5, kc = p & 31;
        const int t = bid + ti * gsz;
        const int mt = t >> 5, nt = t & 31;
        if (p >= STAGES) {
            MBAR_WAIT(mbar_base + 16 * s + 8, (u - 1) & 1);  // prior use consumed
        }
        const uint32_t mfull = mbar_base + 16 * s;
        const uint32_t sa = smem_base + s * STAGE_BYTES;
        MBARRIER_EXPECT_TX(mfull, STAGE_BYTES);
        bulk_g2s(sa, g_Aq + (((size_t)mt * K_CHUNKS + kc) << 14), A_BYTES, mfull);
        bulk_g2s(sa + A_BYTES, g_Bq + (((size_t)nt * K_CHUNKS + kc) << 14), B_BYTES, mfull);
    };

    // accumulators: 64 regs
    float d[2][8][4];
#pragma unroll
    for (int i = 0; i < 2; i++)
#pragma unroll
        for (int j = 0; j < 8; j++)
#pragma unroll
            for (int q = 0; q < 4; q++) d[i][j][q] = 0.0f;

    if (tid == 0) {
        produce(0, 0, 0);
        produce(1, 1, 0);
    }

    // precomputed swizzled fragment offsets
    const int lr = l & 15, lk = l >> 4;
    const int rowA0 = (warp_m + lr) * 128;
    const int rowB0 = (warp_n + lr) * 128;
    const int rxA = (warp_m + lr) & 7;
    const int rxB = (warp_n + lr) & 7;
    int offA[4], offB[4];
#pragma unroll
    for (int ks = 0; ks < 4; ks++) {
        const int kg = ks * 2 + lk;
        offA[ks] = rowA0 + ((((kg ^ rxA) & 7)) << 4);
        offB[ks] = rowB0 + ((((kg ^ rxB) & 7)) << 4);
    }

    const float inv = 1.0f / (xs[0] * ws[0]);
    const int erow = warp_m + (l >> 2);
    const int ecol = warp_n + 2 * (l & 3);

    int s_cons = 0, u_cons = 0;
    int s_prod = 2, u_prod = 0;

#pragma unroll 1
    for (int p = 0; p < L; ++p) {
        if (p + 2 < L) {
            if (tid == 0) produce(p + 2, s_prod, u_prod);
            if (++s_prod == STAGES) { s_prod = 0; ++u_prod; }
        }

        MBAR_WAIT(mbar_base + 16 * s_cons, u_cons & 1);      // stage full (tx done)

        const uint32_t sa = smem_base + s_cons * STAGE_BYTES;
        const uint32_t sb = sa + A_BYTES;

#pragma unroll
        for (int ks = 0; ks < 4; ++ks) {
            uint32_t a[2][4], bf[4][4];
#pragma unroll
            for (int mi = 0; mi < 2; mi++)
                ldmatrix_x4(a[mi][0], a[mi][1], a[mi][2], a[mi][3],
                            sa + offA[ks] + mi * (16 * 128));
#pragma unroll
            for (int j = 0; j < 4; j++)
                ldmatrix_x4(bf[j][0], bf[j][1], bf[j][2], bf[j][3],
                            sb + offB[ks] + j * (16 * 128));
#pragma unroll
            for (int mi = 0; mi < 2; mi++)
#pragma unroll
                for (int nj = 0; nj < 8; nj++) {
                    const int j = nj >> 1, h = nj & 1;
                    mma_e4m3(d[mi][nj], a[mi], bf[j][h], bf[j][2 + h]);
                }
        }
        MBARRIER_ARRIVE(mbar_base + 16 * s_cons + 8);        // stage empty
        if (++s_cons == STAGES) { s_cons = 0; ++u_cons; }

        // ---- tile boundary: epilogue + accumulator reset ----
        if ((p & 31) == 31) {
            const int t = bid + (p >> 5) * gsz;
            const int mt = t >> 5, nt = t & 31;
            const int mrow = mt * BM + erow;
            const int ncol0 = nt * BN + ecol;
#pragma unroll
            for (int nj = 0; nj < 8; nj++) {
                const int n = ncol0 + nj * 8;
                const float b0 = bias[n];
                const float b1 = bias[n + 1];
#pragma unroll
                for (int mi = 0; mi < 2; mi++) {
                    const int m0 = mrow + mi * 16;
                    float f0 = __bfloat162float(__float2bfloat16_rn(d[mi][nj][0] * inv + b0));
                    float f1 = __bfloat162float(__float2bfloat16_rn(d[mi][nj][1] * inv + b1));
                    float f2 = __bfloat162float(__float2bfloat16_rn(d[mi][nj][2] * inv + b0));
                    float f3 = __bfloat162float(__float2bfloat16_rn(d[mi][nj][3] * inv + b1));
                    *reinterpret_cast<float2*>(out + (size_t)m0 * GN + n) = make_float2(f0, f1);
                    *reinterpret_cast<float2*>(out + (size_t)(m0 + 8) * GN + n) = make_float2(f2, f3);
                }
            }
#pragma unroll
            for (int i = 0; i < 2; i++)
#pragma unroll
                for (int j = 0; j < 8; j++)
#pragma unroll
                    for (int q = 0; q < 4; q++) d[i][j][q] = 0.0f;
        }
    }
}

// ============================================================================
// kernel_launch — inputs identified by element count
// ============================================================================
extern "C" void kernel_launch(void* const* d_in, const int* in_sizes, int n_in,
                              void* d_out, int out_size) {
    const float* x = nullptr;
    const float* wgt = nullptr;
    const float* bias = nullptr;
    const float* scales[3] = {nullptr, nullptr, nullptr};
    int ns = 0;
    for (int i = 0; i < n_in; i++) {
        const int sz = in_sizes[i];
        if (sz == GM * GK)      x    = (const float*)d_in[i];
        else if (sz == GN * GK) wgt  = (const float*)d_in[i];
        else if (sz == GN)      bias = (const float*)d_in[i];
        else if (sz == 1 && ns < 3) scales[ns++] = (const float*)d_in[i];
    }
    const float* xs = scales[0];
    const float* ws = scales[1];
    float* out = (float*)d_out;

    {
        const int total = X_TOTAL8 + W_TOTAL8;
        quant_both_kernel<<<total / 256, 256>>>(x, wgt, xs, ws);
    }

    int sms = 148;
    cudaDeviceGetAttribute(&sms, cudaDevAttrMultiProcessorCount, 0);
    int grid = 2 * sms;
    if (grid > NTILES) grid = NTILES;

    cudaFuncSetAttribute(gemm_kernel, cudaFuncAttributeMaxDynamicSharedMemorySize, SMEM_TOTAL);
    gemm_kernel<<<grid, THREADS, SMEM_TOTAL>>>(bias, xs, ws, out);
}